// round 1
// baseline (speedup 1.0000x reference)
#include <cuda_runtime.h>

// ---------------------------------------------------------------------------
// TemporalGNN collapsed form (H0 == 0 throughout the scan):
//   y = A_hat x               (one normalized-adjacency aggregation, F_IN=2 ch)
//   per node/t:  Hn = (1 - sigmoid(y_t @ Mz + cz)) * tanh(y_t @ Mh + ch)
//   acc = sum_t p_t * Hn ;  out = relu(acc) @ head_w + head_b
// where Mz = conv_z_w @ lin_z_w[:32], cz = conv_z_b @ lin_z_w[:32] + lin_z_b
// (same for h gate). R gate is dead (H0 * R == 0).
// ---------------------------------------------------------------------------

#define NB 4
#define NN 30000
#define NF 2
#define NT 12
#define NH 32
#define NO 12
#define NE 240000
#define NODE_W (NF * NT) /* 24 floats per (b,node) */

__device__ float g_dinv[NN];
__device__ float g_y[(size_t)NB * NN * NODE_W];
__device__ float g_Mz[2 * NH];
__device__ float g_Mh[2 * NH];
__device__ float g_cz[NH];
__device__ float g_ch[NH];
__device__ float g_p[NT];

// deg[n] starts at 1 (self loop), atomically add dst occurrences, then rsqrt.
__global__ void k_deg_init() {
    int i = blockIdx.x * blockDim.x + threadIdx.x;
    if (i < NN) g_dinv[i] = 1.0f;
}

__global__ void k_deg_acc(const int* __restrict__ ei) {
    int e = blockIdx.x * blockDim.x + threadIdx.x;
    if (e < NE) atomicAdd(&g_dinv[ei[NE + e]], 1.0f);
}

__global__ void k_dinv() {
    int i = blockIdx.x * blockDim.x + threadIdx.x;
    if (i < NN) g_dinv[i] = rsqrtf(g_dinv[i]);
}

// Fuse conv weights into lin weights; softmax the attention. One tiny block.
__global__ void k_setup(const float* __restrict__ att,
                        const float* __restrict__ czw, const float* __restrict__ czb,
                        const float* __restrict__ lzw, const float* __restrict__ lzb,
                        const float* __restrict__ chw, const float* __restrict__ chb,
                        const float* __restrict__ lhw, const float* __restrict__ lhb) {
    int t = threadIdx.x;
    if (t == 0) {
        float m = -1e30f;
        for (int i = 0; i < NT; i++) m = fmaxf(m, att[i]);
        float e[NT], s = 0.f;
        for (int i = 0; i < NT; i++) { e[i] = __expf(att[i] - m); s += e[i]; }
        float inv = 1.0f / s;
        for (int i = 0; i < NT; i++) g_p[i] = e[i] * inv;
    }
    if (t < NH) {
        int h = t;
        float m0 = 0.f, m1 = 0.f, c = lzb[h];
        for (int k = 0; k < NH; k++) {
            float w = lzw[k * NH + h];
            m0 = fmaf(czw[k], w, m0);
            m1 = fmaf(czw[NH + k], w, m1);
            c = fmaf(czb[k], w, c);
        }
        g_Mz[h] = m0; g_Mz[NH + h] = m1; g_cz[h] = c;
    } else if (t < 2 * NH) {
        int h = t - NH;
        float m0 = 0.f, m1 = 0.f, c = lhb[h];
        for (int k = 0; k < NH; k++) {
            float w = lhw[k * NH + h];
            m0 = fmaf(chw[k], w, m0);
            m1 = fmaf(chw[NH + k], w, m1);
            c = fmaf(chb[k], w, c);
        }
        g_Mh[h] = m0; g_Mh[NH + h] = m1; g_ch[h] = c;
    }
}

// Self-loop term: y = dinv[n]^2 * x  (writes every element of y; no memset needed)
__global__ void k_selfloop(const float* __restrict__ x) {
    size_t i = (size_t)blockIdx.x * blockDim.x + threadIdx.x;
    if (i < (size_t)NB * NN * NODE_W) {
        int node = (int)((i / NODE_W) % NN);
        float d = g_dinv[node];
        g_y[i] = d * d * x[i];
    }
}

// Edge scatter: per (edge, batch, quad-of-4-floats). 24 consecutive threads
// per edge -> coalesced 96B reads of src node data, coalesced atomics at dst.
__global__ void k_scatter(const float* __restrict__ x, const int* __restrict__ ei) {
    size_t tid = (size_t)blockIdx.x * blockDim.x + threadIdx.x;
    if (tid >= (size_t)NE * 24) return;
    int e = (int)(tid / 24);
    int q = (int)(tid % 24);
    int b = q / 6, j = q % 6;
    int s = ei[e];
    int d = ei[NE + e];
    float norm = g_dinv[s] * g_dinv[d];
    const float4 xv = *(const float4*)(x + ((size_t)b * NN + s) * NODE_W + j * 4);
    float* yp = g_y + ((size_t)b * NN + d) * NODE_W + j * 4;
    atomicAdd(yp + 0, norm * xv.x);
    atomicAdd(yp + 1, norm * xv.y);
    atomicAdd(yp + 2, norm * xv.z);
    atomicAdd(yp + 3, norm * xv.w);
}

// Pointwise GRU-collapse + head GEMV. One thread per (b, node).
__global__ void __launch_bounds__(256)
k_node(const float* __restrict__ hw, const float* __restrict__ hb,
       float* __restrict__ out) {
    __shared__ float s_Mz[2 * NH], s_Mh[2 * NH], s_cz[NH], s_ch[NH], s_p[NT];
    __shared__ float s_hw[NH * NO], s_hb[NO];
    int tid = threadIdx.x;
    for (int i = tid; i < 2 * NH; i += blockDim.x) { s_Mz[i] = g_Mz[i]; s_Mh[i] = g_Mh[i]; }
    for (int i = tid; i < NH; i += blockDim.x) { s_cz[i] = g_cz[i]; s_ch[i] = g_ch[i]; }
    for (int i = tid; i < NT; i += blockDim.x) s_p[i] = g_p[i];
    for (int i = tid; i < NH * NO; i += blockDim.x) s_hw[i] = hw[i];
    for (int i = tid; i < NO; i += blockDim.x) s_hb[i] = hb[i];
    __syncthreads();

    int gid = blockIdx.x * blockDim.x + tid;
    if (gid >= NB * NN) return;

    const float* yp = g_y + (size_t)gid * NODE_W;

    float acc[NH];
#pragma unroll
    for (int h = 0; h < NH; h++) acc[h] = 0.f;

#pragma unroll 1
    for (int t = 0; t < NT; t++) {
        float p = s_p[t];
        float a = yp[t];        // y[.., f=0, t]   (L1-resident after first iter)
        float bb = yp[NT + t];  // y[.., f=1, t]
#pragma unroll
        for (int h = 0; h < NH; h++) {
            float az = fmaf(bb, s_Mz[NH + h], fmaf(a, s_Mz[h], s_cz[h]));
            float ah = fmaf(bb, s_Mh[NH + h], fmaf(a, s_Mh[h], s_ch[h]));
            az = fminf(fmaxf(az, -30.f), 30.f);
            ah = fminf(fmaxf(ah, -15.f), 15.f);
            // (1 - sigmoid(az)) * tanh(ah)  ==  (eb-1) / ((1+ea)*(1+eb))
            float ea = __expf(az);
            float eb = __expf(2.0f * ah);
            float val = __fdividef(eb - 1.0f, (1.0f + ea) * (1.0f + eb));
            acc[h] = fmaf(p, val, acc[h]);
        }
    }

    float o[NO];
#pragma unroll
    for (int j = 0; j < NO; j++) o[j] = s_hb[j];
#pragma unroll
    for (int h = 0; h < NH; h++) {
        float r = fmaxf(acc[h], 0.f);
#pragma unroll
        for (int j = 0; j < NO; j++) o[j] = fmaf(r, s_hw[h * NO + j], o[j]);
    }
    float* op = out + (size_t)gid * NO;
#pragma unroll
    for (int j = 0; j < NO; j++) op[j] = o[j];
}

extern "C" void kernel_launch(void* const* d_in, const int* in_sizes, int n_in,
                              void* d_out, int out_size) {
    const float* x   = (const float*)d_in[0];
    const int*   ei  = (const int*)d_in[1];
    const float* att = (const float*)d_in[2];
    const float* czw = (const float*)d_in[3];
    const float* czb = (const float*)d_in[4];
    const float* lzw = (const float*)d_in[5];
    const float* lzb = (const float*)d_in[6];
    // d_in[7..10] = conv_r_*, lin_r_* : dead code (H0 == 0 -> H0*R == 0)
    const float* chw = (const float*)d_in[11];
    const float* chb = (const float*)d_in[12];
    const float* lhw = (const float*)d_in[13];
    const float* lhb = (const float*)d_in[14];
    const float* hw  = (const float*)d_in[15];
    const float* hb  = (const float*)d_in[16];
    float* out = (float*)d_out;

    k_deg_init<<<(NN + 255) / 256, 256>>>();
    k_deg_acc<<<(NE + 255) / 256, 256>>>(ei);
    k_dinv<<<(NN + 255) / 256, 256>>>();
    k_setup<<<1, 64>>>(att, czw, czb, lzw, lzb, chw, chb, lhw, lhb);

    size_t ytot = (size_t)NB * NN * NODE_W;
    k_selfloop<<<(unsigned)((ytot + 255) / 256), 256>>>(x);

    size_t stot = (size_t)NE * 24;
    k_scatter<<<(unsigned)((stot + 255) / 256), 256>>>(x, ei);

    k_node<<<(NB * NN + 255) / 256, 256>>>(hw, hb, out);
}

// round 2
// speedup vs baseline: 1.8095x; 1.8095x over previous
#include <cuda_runtime.h>

// ---------------------------------------------------------------------------
// Collapsed TemporalGNN (H0 == 0 throughout the scan; R gate dead):
//   y    = A_hat x                        (normalized adjacency, per b,f,t)
//   Hn   = (1 - sigmoid(y@Mz + cz)) * tanh(y@Mh + ch)
//        = 0.5*(1 - tanh((y@Mz + cz)/2)) * tanh(y@Mh + ch)
//   acc  = sum_t p_t * Hn ;  out = relu(acc) @ head_w + head_b
// Mz/cz pre-scaled by 0.5 and p pre-scaled by 0.5 at setup so the node kernel
// is exactly 2 tanh.approx + 6 FMA per (t,h).
// ---------------------------------------------------------------------------

#define NB 4
#define NN 30000
#define NT 12
#define NH 32
#define NO 12
#define NE 240000
#define NODE_W 24               /* F_IN(2) * T(12) floats per (b,node) */
#define DEG_BLOCKS ((NN + 255) / 256)

__device__ float g_deg[NN];
__device__ float g_y[(size_t)NB * NN * NODE_W];
__device__ float g_Mz[2 * NH];
__device__ float g_Mh[2 * NH];
__device__ float g_cz[NH];
__device__ float g_ch[NH];
__device__ float g_p[NT];

__device__ __forceinline__ float tanh_approx(float x) {
    float r;
    asm("tanh.approx.f32 %0, %1;" : "=f"(r) : "f"(x));
    return r;
}

// Blocks [0, DEG_BLOCKS): deg = 1 (self loop). Block DEG_BLOCKS: fused-weight
// setup (warp-per-output-column with shuffle reduction) + softmax.
__global__ void k_init(const float* __restrict__ att,
                       const float* __restrict__ czw, const float* __restrict__ czb,
                       const float* __restrict__ lzw, const float* __restrict__ lzb,
                       const float* __restrict__ chw, const float* __restrict__ chb,
                       const float* __restrict__ lhw, const float* __restrict__ lhb) {
    if (blockIdx.x < DEG_BLOCKS) {
        int i = blockIdx.x * 256 + threadIdx.x;
        if (i < NN) g_deg[i] = 1.0f;
        return;
    }
    int lane = threadIdx.x & 31;
    int warp = threadIdx.x >> 5;

    if (threadIdx.x == 0) {
        float m = -1e30f;
        for (int i = 0; i < NT; i++) m = fmaxf(m, att[i]);
        float e[NT], s = 0.f;
        for (int i = 0; i < NT; i++) { e[i] = __expf(att[i] - m); s += e[i]; }
        float inv = 0.5f / s;                    // fold the 0.5 of (1-tz)/2 here
        for (int i = 0; i < NT; i++) g_p[i] = e[i] * inv;
    }

#pragma unroll
    for (int i = warp; i < 2 * NH; i += 8) {
        int gate = i >> 5;                       // 0 = z gate, 1 = h gate
        int h = i & 31;
        const float* cw = gate ? chw : czw;
        const float* cb = gate ? chb : czb;
        const float* lw = gate ? lhw : lzw;
        const float* lb = gate ? lhb : lzb;
        float w = lw[lane * NH + h];             // only first NH rows matter (H0=0)
        float m0 = cw[lane] * w;
        float m1 = cw[NH + lane] * w;
        float c  = cb[lane] * w;
#pragma unroll
        for (int off = 16; off; off >>= 1) {
            m0 += __shfl_xor_sync(0xffffffffu, m0, off);
            m1 += __shfl_xor_sync(0xffffffffu, m1, off);
            c  += __shfl_xor_sync(0xffffffffu, c, off);
        }
        if (lane == 0) {
            c += lb[h];
            if (gate == 0) {                     // tanh(az/2): scale by 0.5
                g_Mz[h] = 0.5f * m0; g_Mz[NH + h] = 0.5f * m1; g_cz[h] = 0.5f * c;
            } else {
                g_Mh[h] = m0; g_Mh[NH + h] = m1; g_ch[h] = c;
            }
        }
    }
}

__global__ void k_deg_acc(const int* __restrict__ ei) {
    int e = blockIdx.x * blockDim.x + threadIdx.x;
    if (e < NE) atomicAdd(&g_deg[ei[NE + e]], 1.0f);
}

// Self-loop term y = x / deg[node], float4-wide (writes every element of y).
__global__ void k_selfloop(const float* __restrict__ x) {
    size_t i = (size_t)blockIdx.x * blockDim.x + threadIdx.x;
    if (i >= (size_t)NB * NN * (NODE_W / 4)) return;
    int node = (int)((i / (NODE_W / 4)) % NN);
    float inv = __fdividef(1.0f, g_deg[node]);   // == rsqrt(deg)^2 to 1e-7
    float4 v = ((const float4*)x)[i];
    v.x *= inv; v.y *= inv; v.z *= inv; v.w *= inv;
    ((float4*)g_y)[i] = v;
}

// Edge scatter: one thread per (edge, batch, quad). One red.global.add.v4.f32
// per thread (4x fewer atomic instructions than scalar REDG).
__global__ void k_scatter(const float* __restrict__ x, const int* __restrict__ ei) {
    size_t tid = (size_t)blockIdx.x * blockDim.x + threadIdx.x;
    if (tid >= (size_t)NE * 24) return;
    int e = (int)(tid / 24);
    int q = (int)(tid % 24);
    int b = q / 6, j = q % 6;
    int s = __ldg(ei + e);
    int d = __ldg(ei + NE + e);
    float norm = rsqrtf(g_deg[s]) * rsqrtf(g_deg[d]);
    const float4 xv = __ldg((const float4*)(x + ((size_t)b * NN + s) * NODE_W + j * 4));
    float* yp = g_y + ((size_t)b * NN + d) * NODE_W + j * 4;
    asm volatile("red.global.add.v4.f32 [%0], {%1, %2, %3, %4};"
                 :: "l"(yp), "f"(norm * xv.x), "f"(norm * xv.y),
                    "f"(norm * xv.z), "f"(norm * xv.w)
                 : "memory");
}

// Pointwise collapse + head GEMV. One thread per (b, node).
// Per (t,h): 2 tanh.approx (MUFU) + 6 FMA. MUFU-roofline ~21us chip-wide.
__global__ void __launch_bounds__(256)
k_node(const float* __restrict__ hw, const float* __restrict__ hb,
       float* __restrict__ out) {
    __shared__ float s_Mz[2 * NH], s_Mh[2 * NH], s_cz[NH], s_ch[NH], s_p[NT];
    __shared__ float s_hw[NH * NO], s_hb[NO];
    int tid = threadIdx.x;
    for (int i = tid; i < 2 * NH; i += 256) { s_Mz[i] = g_Mz[i]; s_Mh[i] = g_Mh[i]; }
    if (tid < NH) { s_cz[tid] = g_cz[tid]; s_ch[tid] = g_ch[tid]; }
    if (tid < NT) s_p[tid] = g_p[tid];
    for (int i = tid; i < NH * NO; i += 256) s_hw[i] = hw[i];
    if (tid < NO) s_hb[tid] = hb[tid];
    __syncthreads();

    int gid = blockIdx.x * 256 + tid;
    if (gid >= NB * NN) return;

    float yv[NODE_W];
    const float4* yp4 = (const float4*)(g_y + (size_t)gid * NODE_W);
#pragma unroll
    for (int i = 0; i < NODE_W / 4; i++) {
        float4 v = yp4[i];
        yv[4 * i + 0] = v.x; yv[4 * i + 1] = v.y;
        yv[4 * i + 2] = v.z; yv[4 * i + 3] = v.w;
    }

    float acc[NH];
#pragma unroll
    for (int h = 0; h < NH; h++) acc[h] = 0.f;

#pragma unroll 1
    for (int t = 0; t < NT; t++) {
        float hp = s_p[t];                        // 0.5 * softmax prob
        float a  = yv[t];
        float bb = yv[NT + t];
#pragma unroll
        for (int h = 0; h < NH; h++) {
            float az = fmaf(a, s_Mz[h], fmaf(bb, s_Mz[NH + h], s_cz[h]));
            float ah = fmaf(a, s_Mh[h], fmaf(bb, s_Mh[NH + h], s_ch[h]));
            float tz = tanh_approx(az);           // tanh((y@Mz+cz)/2)
            float th = tanh_approx(ah);
            float u  = fmaf(-tz, th, th);         // (1 - tz) * th
            acc[h]   = fmaf(hp, u, acc[h]);
        }
    }

    float o[NO];
#pragma unroll
    for (int j = 0; j < NO; j++) o[j] = s_hb[j];
#pragma unroll
    for (int h = 0; h < NH; h++) {
        float r = fmaxf(acc[h], 0.f);
#pragma unroll
        for (int j = 0; j < NO; j++) o[j] = fmaf(r, s_hw[h * NO + j], o[j]);
    }
    float4* op4 = (float4*)(out + (size_t)gid * NO);
#pragma unroll
    for (int j = 0; j < NO / 4; j++)
        op4[j] = make_float4(o[4 * j], o[4 * j + 1], o[4 * j + 2], o[4 * j + 3]);
}

extern "C" void kernel_launch(void* const* d_in, const int* in_sizes, int n_in,
                              void* d_out, int out_size) {
    const float* x   = (const float*)d_in[0];
    const int*   ei  = (const int*)d_in[1];
    const float* att = (const float*)d_in[2];
    const float* czw = (const float*)d_in[3];
    const float* czb = (const float*)d_in[4];
    const float* lzw = (const float*)d_in[5];
    const float* lzb = (const float*)d_in[6];
    // d_in[7..10] = conv_r_*, lin_r_* : dead (H0 == 0 -> H0*R == 0)
    const float* chw = (const float*)d_in[11];
    const float* chb = (const float*)d_in[12];
    const float* lhw = (const float*)d_in[13];
    const float* lhb = (const float*)d_in[14];
    const float* hw  = (const float*)d_in[15];
    const float* hb  = (const float*)d_in[16];
    float* out = (float*)d_out;

    k_init<<<DEG_BLOCKS + 1, 256>>>(att, czw, czb, lzw, lzb, chw, chb, lhw, lhb);
    k_deg_acc<<<(NE + 255) / 256, 256>>>(ei);

    size_t y4 = (size_t)NB * NN * (NODE_W / 4);
    k_selfloop<<<(unsigned)((y4 + 255) / 256), 256>>>(x);

    size_t stot = (size_t)NE * 24;
    k_scatter<<<(unsigned)((stot + 255) / 256), 256>>>(x, ei);

    k_node<<<(NB * NN + 255) / 256, 256>>>(hw, hb, out);
}